// round 17
// baseline (speedup 1.0000x reference)
#include <cuda_runtime.h>
#include <cstdint>

typedef unsigned long long ull;

// Problem constants
#define B_  2048
#define T_  512
#define I_  58
#define KP_ 60          // padded k (multiple of 4)
#define H_  23
#define G_  69          // 3*H
#define GP_ 72          // padded gate dim
#define ROWS_ (B_*T_)   // 1048576

// Scratch for x_proj: [B*T][72] padded
__device__ float g_xproj[(size_t)ROWS_ * GP_];

// ---------------- f32x2 helpers ----------------
__device__ __forceinline__ ull pk2(float a, float b) {
    ull r;
    asm("mov.b64 %0, {%1, %2};" : "=l"(r) : "f"(a), "f"(b));
    return r;
}
__device__ __forceinline__ void upk2(ull v, float& a, float& b) {
    asm("mov.b64 {%0, %1}, %2;" : "=f"(a), "=f"(b) : "l"(v));
}
__device__ __forceinline__ ull ffma2(ull a, ull b, ull c) {
    ull d;
    asm("fma.rn.f32x2 %0, %1, %2, %3;" : "=l"(d) : "l"(a), "l"(b), "l"(c));
    return d;
}
__device__ __forceinline__ ull add2(ull a, ull b) {
    ull d;
    asm("add.rn.f32x2 %0, %1, %2;" : "=l"(d) : "l"(a), "l"(b));
    return d;
}
// ---------------- fast transcendentals ----------------
__device__ __forceinline__ float fex2(float x) {
    float y; asm("ex2.approx.f32 %0, %1;" : "=f"(y) : "f"(x)); return y;
}
__device__ __forceinline__ float frcp(float x) {
    float y; asm("rcp.approx.f32 %0, %1;" : "=f"(y) : "f"(x)); return y;
}
__device__ __forceinline__ float fsigmoid(float x) {
    return frcp(1.0f + fex2(-1.4426950408889634f * x));
}
__device__ __forceinline__ float ftanh(float x) {
    float e = fex2(2.8853900817779268f * x);
    return fmaf(-2.0f, frcp(e + 1.0f), 1.0f);
}

// ============================================================================
// Kernel 1: x_proj = task @ W_ih^T + b_ih
//   96 threads/block, 128 rows/block. Thread = (rg, gg): 8 rows x 6 g-pairs.
//   8 rows per thread halves smem wf per FFMA2 (weights amortized over 2x
//   rows): per k = 12 wf weights + 8 wf x for 48 FFMA2.
//   Unskewed KP=60 layout (proven correct in R7); bias straight from gmem.
// ============================================================================
__global__ __launch_bounds__(96, 2) void gemm_xproj_kernel(
    const float* __restrict__ task,   // [B*T][58]
    const float* __restrict__ Wih,    // [69][58]
    const float* __restrict__ bih)    // [69]
{
    // xs: [128][60] floats (30720B) ; ws: [60][36] ull (17280B) = 48000B
    // restage reuse: os[128][36] ull = 36864B <= 48000B
    __shared__ __align__(16) char sraw[128 * KP_ * 4 + KP_ * 36 * 8];
    float* xs = reinterpret_cast<float*>(sraw);
    ull*   ws = reinterpret_cast<ull*>(sraw + 128 * KP_ * 4);

    const int tid = threadIdx.x;
    const size_t rowbase = (size_t)blockIdx.x * 128;

    // Stage x tile: coalesced float4 loads (1856 vectors), scatter to 60-pad
    {
        const float4* src = reinterpret_cast<const float4*>(task + rowbase * I_);
        #pragma unroll
        for (int it = 0; it < 20; it++) {
            int v = tid + it * 96;
            if (it < 19 || tid < 32) {
                float4 f = src[v];
                int e = 4 * v;
                int r = e / I_, c = e - r * I_;
                float vals[4] = {f.x, f.y, f.z, f.w};
                #pragma unroll
                for (int q = 0; q < 4; q++) {
                    int rr = r, cc = c + q;
                    if (cc >= I_) { rr += 1; cc -= I_; }
                    xs[rr * KP_ + cc] = vals[q];
                }
            }
        }
        // zero pad cols 58,59 (128 rows x 2 = 256 slots)
        for (int i = tid; i < 256; i += 96) {
            int r = i >> 1, c = I_ + (i & 1);
            xs[r * KP_ + c] = 0.0f;
        }
    }
    // Stage weights as (k, g-pair); zero beyond k=57 / g=68
    for (int i = tid; i < KP_ * 36; i += 96) {
        int k = i / 36, p = i - 36 * k;
        int g0 = 2 * p;
        float w0 = (k < I_ && g0     < G_) ? Wih[g0 * I_ + k]       : 0.0f;
        float w1 = (k < I_ && g0 + 1 < G_) ? Wih[(g0 + 1) * I_ + k] : 0.0f;
        ws[i] = pk2(w0, w1);
    }
    __syncthreads();

    const int gg = tid % 6;      // 6 pair-tiles of 6 pairs = 36 pairs = 72 g
    const int rg = tid / 6;      // 16 row groups of 8 rows
    const int r0 = rg * 8;
    const ull* wbase = ws + gg * 6;
    const float* xbase = xs + r0 * KP_;

    // bias init straight from gmem (tiny, L1-resident)
    ull acc[8][6];
    #pragma unroll
    for (int p = 0; p < 6; p++) {
        int P = gg * 6 + p;
        float b0 = (2 * P     < G_) ? bih[2 * P]     : 0.0f;
        float b1 = (2 * P + 1 < G_) ? bih[2 * P + 1] : 0.0f;
        ull bb = pk2(b0, b1);
        #pragma unroll
        for (int i = 0; i < 8; i++) acc[i][p] = bb;
    }

    #pragma unroll 3
    for (int kc = 0; kc < KP_ / 4; kc++) {
        // 8 rows x 4 k's via LDS.128 (240B row stride -> conflict-free phases)
        float4 xq[8];
        #pragma unroll
        for (int i = 0; i < 8; i++)
            xq[i] = *reinterpret_cast<const float4*>(xbase + i * KP_ + kc * 4);

        #pragma unroll
        for (int kk = 0; kk < 4; kk++) {
            const ulonglong2* wk =
                reinterpret_cast<const ulonglong2*>(wbase + (kc * 4 + kk) * 36);
            ulonglong2 wA = wk[0], wB = wk[1], wC = wk[2];
            #pragma unroll
            for (int i = 0; i < 8; i++) {
                float xv = (kk == 0) ? xq[i].x : (kk == 1) ? xq[i].y
                         : (kk == 2) ? xq[i].z : xq[i].w;
                ull X = pk2(xv, xv);
                acc[i][0] = ffma2(X, wA.x, acc[i][0]);
                acc[i][1] = ffma2(X, wA.y, acc[i][1]);
                acc[i][2] = ffma2(X, wB.x, acc[i][2]);
                acc[i][3] = ffma2(X, wB.y, acc[i][3]);
                acc[i][4] = ffma2(X, wC.x, acc[i][4]);
                acc[i][5] = ffma2(X, wC.y, acc[i][5]);
            }
        }
    }

    __syncthreads();   // xs/ws dead; reuse as output stage
    ull* os = reinterpret_cast<ull*>(sraw);   // [128][36] pairs
    #pragma unroll
    for (int i = 0; i < 8; i++) {
        #pragma unroll
        for (int p = 0; p < 6; p++) {
            os[(r0 + i) * 36 + gg * 6 + p] = acc[i][p];
        }
    }
    __syncthreads();
    // Coalesced float4 streamout: 128*72/4 = 2304 vectors, 24 per thread
    {
        const float4* src = reinterpret_cast<const float4*>(sraw);
        float4* dst = reinterpret_cast<float4*>(g_xproj + rowbase * GP_);
        #pragma unroll
        for (int it = 0; it < 24; it++) {
            int idx = tid + it * 96;
            dst[idx] = src[idx];
        }
    }
}

// ============================================================================
// Kernel 2: GRU scan (R7/R15 verbatim — best measured, 214us). 4 warps/block,
//   one batch row per warp, W_hh in registers, 1 syncwarp/step,
//   two parallel accumulator chains per gate, 4-step x prefetch.
// ============================================================================
__global__ __launch_bounds__(128, 4) void gru_scan_kernel(
    const float* __restrict__ Whh,    // [69][23]
    const float* __restrict__ bhh,    // [69]
    const float* __restrict__ piw,    // [23]
    const float* __restrict__ pib,    // [23]
    float* __restrict__ out_action,   // [B][T][23]
    float* __restrict__ out_hidden)   // [B][23]
{
    __shared__ __align__(16) float hsm[4][2][32];

    const int j  = threadIdx.x & 31;
    const int w  = threadIdx.x >> 5;
    const int b  = blockIdx.x * 4 + w;
    const int jc = (j < H_) ? j : (H_ - 1);
    const bool act = (j < H_);

    ull WR[12], WZ[12], WN[12];
    {
        const float* wr = Whh + (size_t)jc * H_;
        const float* wz = Whh + (size_t)(H_ + jc) * H_;
        const float* wn = Whh + (size_t)(2 * H_ + jc) * H_;
        #pragma unroll
        for (int m = 0; m < 11; m++) {
            WR[m] = pk2(wr[2 * m], wr[2 * m + 1]);
            WZ[m] = pk2(wz[2 * m], wz[2 * m + 1]);
            WN[m] = pk2(wn[2 * m], wn[2 * m + 1]);
        }
        WR[11] = pk2(wr[22], bhh[jc]);
        WZ[11] = pk2(wz[22], bhh[H_ + jc]);
        WN[11] = pk2(wn[22], bhh[2 * H_ + jc]);
    }
    const float pw = piw[jc], pb = pib[jc];

    hsm[w][0][j] = (j == 23) ? 1.0f : 0.0f;
    hsm[w][1][j] = (j == 23) ? 1.0f : 0.0f;
    __syncwarp();

    const float* xp = g_xproj + (size_t)b * T_ * GP_;
    float* outp = out_action + (size_t)b * T_ * H_;
    const int o0 = jc, o1 = H_ + jc, o2 = 2 * H_ + jc;

    float cur[12];
    #pragma unroll
    for (int s = 0; s < 4; s++) {
        const float* xr = xp + s * GP_;
        cur[3 * s + 0] = xr[o0];
        cur[3 * s + 1] = xr[o1];
        cur[3 * s + 2] = xr[o2];
    }

    float h = 0.0f;

    #pragma unroll 2
    for (int tb = 0; tb < T_; tb += 4) {
        const float* xn_ = xp + (size_t)((tb + 4 < T_) ? tb + 4 : T_ - 4) * GP_;
        #pragma unroll
        for (int s = 0; s < 4; s++) {
            const ulonglong2* hq =
                reinterpret_cast<const ulonglong2*>(hsm[w][s & 1]);
            ull aR0 = 0, aR1 = 0, aZ0 = 0, aZ1 = 0, aN0 = 0, aN1 = 0;
            #pragma unroll
            for (int m = 0; m < 6; m++) {
                ulonglong2 q = hq[m];
                aR0 = ffma2(WR[2 * m],     q.x, aR0);
                aR1 = ffma2(WR[2 * m + 1], q.y, aR1);
                aZ0 = ffma2(WZ[2 * m],     q.x, aZ0);
                aZ1 = ffma2(WZ[2 * m + 1], q.y, aZ1);
                aN0 = ffma2(WN[2 * m],     q.x, aN0);
                aN1 = ffma2(WN[2 * m + 1], q.y, aN1);
            }
            ull aR = add2(aR0, aR1);
            ull aZ = add2(aZ0, aZ1);
            ull aN = add2(aN0, aN1);
            float rl, rh, zl, zh, nl, nh;
            upk2(aR, rl, rh); upk2(aZ, zl, zh); upk2(aN, nl, nh);

            float r = fsigmoid(cur[3 * s + 0] + (rl + rh));
            float z = fsigmoid(cur[3 * s + 1] + (zl + zh));
            float n = ftanh(fmaf(r, nl + nh, cur[3 * s + 2]));
            float hnew = fmaf(z, h - n, n);        // (1-z)*n + z*h

            if (act) hsm[w][(s + 1) & 1][j] = hnew;
            __syncwarp();

            if (act) outp[(size_t)(tb + s) * H_ + j] = fmaf(pw, hnew, pb);
            h = hnew;

            cur[3 * s + 0] = xn_[s * GP_ + o0];
            cur[3 * s + 1] = xn_[s * GP_ + o1];
            cur[3 * s + 2] = xn_[s * GP_ + o2];
        }
    }

    if (act) out_hidden[(size_t)b * H_ + j] = h;
}

// ============================================================================
extern "C" void kernel_launch(void* const* d_in, const int* in_sizes, int n_in,
                              void* d_out, int out_size) {
    const float* task = (const float*)d_in[0];  // (2048,512,58)
    const float* Wih  = (const float*)d_in[1];  // (69,58)
    const float* Whh  = (const float*)d_in[2];  // (69,23)
    const float* bih  = (const float*)d_in[3];  // (69)
    const float* bhh  = (const float*)d_in[4];  // (69)
    const float* piw  = (const float*)d_in[5];  // (23)
    const float* pib  = (const float*)d_in[6];  // (23)

    float* out = (float*)d_out;
    float* action = out;                                  // B*T*H
    float* hidden = out + (size_t)B_ * T_ * H_;           // B*H

    gemm_xproj_kernel<<<ROWS_ / 128, 96>>>(task, Wih, bih);
    gru_scan_kernel<<<B_ / 4, 128>>>(Whh, bhh, piw, pib, action, hidden);
}